// round 3
// baseline (speedup 1.0000x reference)
#include <cuda_runtime.h>
#include <cuda_bf16.h>
#include <mma.h>

using namespace nvcuda;

#define BB 4
#define NN 4096
#define DIMV 128
#define DE 512
#define TOT (BB * NN)          // 16384 rows
#define CHUNK 16
#define NCHUNK (NN / CHUNK)    // 256

// Scratch (allocation-free: __device__ globals)
// g_sh per row: [0,512) = sigmoid(s) (gate), [512,1024) = gelu(h)
__device__ float g_sh[(size_t)TOT * 1024];
__device__ float g_o[(size_t)TOT * DE];      // gated aggregation, input to final GEMM
__device__ float g_part[BB * NCHUNK * DE];   // chunk partial sums -> exclusive offsets

#define BK 32
#define PAD 36                  // smem pitch (floats), multiple of 4

__device__ __forceinline__ float gelu_exact(float x) {
    return 0.5f * x * (1.0f + erff(x * 0.70710678118654752f));
}
__device__ __forceinline__ float sigmoid_f(float x) {
    return 1.0f / (1.0f + expf(-x));
}

// ---------------------------------------------------------------------------
// tf32 wmma GEMM, 128x128 tile per block (256 threads, 8 warps of 32x64).
//   out[m, j] = op( sum_k A[m,k] * W[j,k] + bias[j] )
// W row-major [Ntot, K]. Split weight at splitJ (W1/bias1/op1 beyond it).
// op: 0 = none, 1 = sigmoid, 2 = gelu(exact)
// ---------------------------------------------------------------------------
__global__ __launch_bounds__(256) void gemm_tf32_kernel(
    const float* __restrict__ A, int lda,
    const float* __restrict__ W0, const float* __restrict__ bias0, int op0,
    const float* __restrict__ W1, const float* __restrict__ bias1, int op1,
    int splitJ, int K,
    float* __restrict__ out, int ldo)
{
    __shared__ float smem_all[2 * 128 * PAD];   // 36 KB
    float* sa = smem_all;                        // A tile: 128 x BK
    float* sb = smem_all + 128 * PAD;            // W tile: 128 x BK

    const int m0 = blockIdx.x * 128;
    const int j0 = blockIdx.y * 128;

    const float* W = W0;
    const float* bias = bias0;
    int op = op0;
    int jw = j0;
    if (j0 >= splitJ) { W = W1; bias = bias1; op = op1; jw = j0 - splitJ; }

    const int tid  = threadIdx.x;
    const int warp = tid >> 5;
    const int lane = tid & 31;
    const int wm = (warp & 3) * 32;   // warp row offset in tile
    const int wn = (warp >> 2) * 64;  // warp col offset in tile

    wmma::fragment<wmma::accumulator, 16, 16, 8, float> c[2][4];
    #pragma unroll
    for (int i = 0; i < 2; i++)
        #pragma unroll
        for (int j = 0; j < 4; j++)
            wmma::fill_fragment(c[i][j], 0.0f);

    for (int kb = 0; kb < K; kb += BK) {
        // Load A tile 128xBK and W tile 128xBK (float4, coalesced)
        #pragma unroll
        for (int i = 0; i < 4; i++) {
            int idx = tid + i * 256;       // 0..1023
            int r  = idx >> 3;             // 0..127
            int c4 = (idx & 7) << 2;       // 0..28 step 4
            float4 va = *reinterpret_cast<const float4*>(
                &A[(size_t)(m0 + r) * lda + kb + c4]);
            *reinterpret_cast<float4*>(&sa[r * PAD + c4]) = va;
            float4 vb = *reinterpret_cast<const float4*>(
                &W[(size_t)(jw + r) * K + kb + c4]);
            *reinterpret_cast<float4*>(&sb[r * PAD + c4]) = vb;
        }
        __syncthreads();

        #pragma unroll
        for (int kk = 0; kk < BK; kk += 8) {
            wmma::fragment<wmma::matrix_a, 16, 16, 8, wmma::precision::tf32, wmma::row_major> af[2];
            wmma::fragment<wmma::matrix_b, 16, 16, 8, wmma::precision::tf32, wmma::col_major> bf[4];
            #pragma unroll
            for (int mf = 0; mf < 2; mf++) {
                wmma::load_matrix_sync(af[mf], &sa[(wm + mf * 16) * PAD + kk], PAD);
                #pragma unroll
                for (int t = 0; t < af[mf].num_elements; t++)
                    af[mf].x[t] = wmma::__float_to_tf32(af[mf].x[t]);
            }
            #pragma unroll
            for (int nf = 0; nf < 4; nf++) {
                wmma::load_matrix_sync(bf[nf], &sb[(wn + nf * 16) * PAD + kk], PAD);
                #pragma unroll
                for (int t = 0; t < bf[nf].num_elements; t++)
                    bf[nf].x[t] = wmma::__float_to_tf32(bf[nf].x[t]);
            }
            #pragma unroll
            for (int mf = 0; mf < 2; mf++)
                #pragma unroll
                for (int nf = 0; nf < 4; nf++)
                    wmma::mma_sync(c[mf][nf], af[mf], bf[nf], c[mf][nf]);
        }
        __syncthreads();
    }

    // Epilogue: per-warp smem staging (32x16 at pitch 20), bias + op, store.
    float* stage = smem_all + warp * 640;  // 8 * 640 = 5120 floats, fits
    #pragma unroll
    for (int nf = 0; nf < 4; nf++) {
        wmma::store_matrix_sync(stage,           c[0][nf], 20, wmma::mem_row_major);
        wmma::store_matrix_sync(stage + 16 * 20, c[1][nf], 20, wmma::mem_row_major);
        __syncwarp();
        #pragma unroll
        for (int i = 0; i < 16; i++) {
            int idx = lane + i * 32;       // 0..511
            int r   = idx >> 4;            // 0..31
            int col = idx & 15;            // 0..15
            float v = stage[r * 20 + col] + bias[jw + wn + nf * 16 + col];
            if (op == 1)      v = sigmoid_f(v);
            else if (op == 2) v = gelu_exact(v);
            out[(size_t)(m0 + wm + r) * ldo + j0 + wn + nf * 16 + col] = v;
        }
        __syncwarp();
    }
}

// ---------------------------------------------------------------------------
// Pass A: per-chunk sums of the combined-gelu h (gelu already applied).
// Thread d in [0,256): lo = g[d], hi = g[d] * g[d+256]
// ---------------------------------------------------------------------------
__global__ __launch_bounds__(256) void chunk_sum_kernel() {
    const int b  = blockIdx.x / NCHUNK;
    const int ch = blockIdx.x % NCHUNK;
    const int d  = threadIdx.x;  // 0..255

    float s_lo = 0.0f, s_hi = 0.0f;
    size_t base = ((size_t)(b * NN + ch * CHUNK)) * 1024 + 512;
    #pragma unroll 4
    for (int r = 0; r < CHUNK; r++) {
        float g1 = g_sh[base + (size_t)r * 1024 + d];
        float g2 = g_sh[base + (size_t)r * 1024 + 256 + d];
        s_lo += g1;
        s_hi += g1 * g2;
    }
    int pb = (b * NCHUNK + ch) * DE;
    g_part[pb + d]       = s_lo;
    g_part[pb + 256 + d] = s_hi;
}

// ---------------------------------------------------------------------------
// Block-parallel exclusive scan of chunk partials along the chunk axis.
// One 256-thread block per (b, d) pair; threadIdx.x = chunk index.
// ---------------------------------------------------------------------------
__global__ __launch_bounds__(256) void scan_part_kernel() {
    const int b = blockIdx.x / DE;
    const int d = blockIdx.x % DE;
    const int c = threadIdx.x;          // 0..255 == NCHUNK
    const int lane = c & 31;
    const int wid  = c >> 5;

    int idx = (b * NCHUNK + c) * DE + d;
    float v = g_part[idx];

    float x = v;
    #pragma unroll
    for (int off = 1; off < 32; off <<= 1) {
        float y = __shfl_up_sync(0xFFFFFFFFu, x, off);
        if (lane >= off) x += y;
    }

    __shared__ float wsum[8];
    if (lane == 31) wsum[wid] = x;
    __syncthreads();

    __shared__ float woff[8];
    if (wid == 0 && lane < 8) {
        float t = wsum[lane];
        #pragma unroll
        for (int off = 1; off < 8; off <<= 1) {
            float y = __shfl_up_sync(0xFFu, t, off);
            if (lane >= off) t += y;
        }
        woff[lane] = t;
    }
    __syncthreads();

    float base = (wid == 0) ? 0.0f : woff[wid - 1];
    g_part[idx] = base + x - v;   // exclusive prefix
}

// ---------------------------------------------------------------------------
// Pass B: within-chunk inclusive scan with exclusive offset, then
//   o = gate * agg / (m+1 + 1e-7)    (gate = sigmoid(s), precomputed)
// ---------------------------------------------------------------------------
__global__ __launch_bounds__(256) void scan_apply_kernel() {
    const int b  = blockIdx.x / NCHUNK;
    const int ch = blockIdx.x % NCHUNK;
    const int d  = threadIdx.x;  // 0..255

    int pb = (b * NCHUNK + ch) * DE;
    float run_lo = g_part[pb + d];
    float run_hi = g_part[pb + 256 + d];

    #pragma unroll 4
    for (int r = 0; r < CHUNK; r++) {
        int n = ch * CHUNK + r;
        size_t row = (size_t)(b * NN + n);
        float g1 = g_sh[row * 1024 + 512 + d];
        float g2 = g_sh[row * 1024 + 768 + d];
        run_lo += g1;
        run_hi += g1 * g2;

        float rec = 1.0f / ((float)(n + 1) + 1e-7f);
        float gate1 = g_sh[row * 1024 + d];
        float gate2 = g_sh[row * 1024 + 256 + d];
        g_o[row * DE + d]       = gate1 * run_lo * rec;
        g_o[row * DE + 256 + d] = gate2 * run_hi * rec;
    }
}

// ---------------------------------------------------------------------------
// Launcher
// Inputs: xq, mask(unused: causal tril by construction),
//         W_se, b_se, W_po, b_po, W_ag, b_ag
// ---------------------------------------------------------------------------
extern "C" void kernel_launch(void* const* d_in, const int* in_sizes, int n_in,
                              void* d_out, int out_size) {
    const float* xq   = (const float*)d_in[0];
    const float* W_se = (const float*)d_in[2];
    const float* b_se = (const float*)d_in[3];
    const float* W_po = (const float*)d_in[4];
    const float* b_po = (const float*)d_in[5];
    const float* W_ag = (const float*)d_in[6];
    const float* b_ag = (const float*)d_in[7];
    float* out = (float*)d_out;

    float* sh_ptr = nullptr;
    float* o_ptr  = nullptr;
    cudaGetSymbolAddress((void**)&sh_ptr, g_sh);
    cudaGetSymbolAddress((void**)&o_ptr, g_o);

    // GEMM1+2 fused: [16384,128] x [1024,128]^T -> gate | gelu(h)
    {
        dim3 grid(TOT / 128, 1024 / 128);
        gemm_tf32_kernel<<<grid, 256>>>(
            xq, DIMV,
            W_se, b_se, /*op=*/1,
            W_po, b_po, /*op=*/2,
            /*splitJ=*/DE, /*K=*/DIMV,
            sh_ptr, /*ldo=*/1024);
    }

    chunk_sum_kernel<<<BB * NCHUNK, 256>>>();
    scan_part_kernel<<<BB * DE, 256>>>();
    scan_apply_kernel<<<BB * NCHUNK, 256>>>();

    // GEMM3: [16384,512] x [128,512]^T -> out
    {
        dim3 grid(TOT / 128, DIMV / 128);
        gemm_tf32_kernel<<<grid, 256>>>(
            o_ptr, DE,
            W_ag, b_ag, /*op=*/0,
            W_ag, b_ag, /*op=*/0,
            /*splitJ=*/1 << 30, /*K=*/DE,
            out, /*ldo=*/DIMV);
    }
}

// round 5
// speedup vs baseline: 1.2323x; 1.2323x over previous
#include <cuda_runtime.h>
#include <cuda_bf16.h>
#include <mma.h>
#include <cstdint>

using namespace nvcuda;

#define BB 4
#define NN 4096
#define DIMV 128
#define DE 512
#define TOT (BB * NN)          // 16384 rows
#define CHUNK 16
#define NCHUNK (NN / CHUNK)    // 256

// Scratch (allocation-free: __device__ globals)
// g_sh per row: [0,512) = sigmoid(s) (gate), [512,1024) = gelu(h)
__device__ float g_sh[(size_t)TOT * 1024];
__device__ float g_o[(size_t)TOT * DE];      // gated aggregation, input to final GEMM
__device__ float g_part[BB * NCHUNK * DE];   // chunk partial sums -> exclusive offsets

// GEMM tiling
#define BM 128
#define BN 64
#define BKG 16
#define PAD 20                  // smem pitch (floats); 80B = mult of 16
#define NSTAGE 3

__device__ __forceinline__ float gelu_exact(float x) {
    return 0.5f * x * (1.0f + erff(x * 0.70710678118654752f));
}
__device__ __forceinline__ float sigmoid_f(float x) {
    return 1.0f / (1.0f + expf(-x));
}

__device__ __forceinline__ void cp_async16(void* smem_dst, const void* gmem_src) {
    unsigned int s = (unsigned int)__cvta_generic_to_shared(smem_dst);
    asm volatile("cp.async.cg.shared.global [%0], [%1], 16;\n" :: "r"(s), "l"(gmem_src));
}
__device__ __forceinline__ void cp_commit() {
    asm volatile("cp.async.commit_group;\n");
}
template <int N>
__device__ __forceinline__ void cp_wait() {
    asm volatile("cp.async.wait_group %0;\n" :: "n"(N));
}

// ---------------------------------------------------------------------------
// tf32 wmma GEMM, 128x64 tile, BK=16, 3-stage cp.async pipeline.
//   out[m, j] = op( sum_k A[m,k] * W[j,k] + bias[j] )
// W row-major [Ntot, K]. Split weight at splitJ. op: 0=none 1=sigmoid 2=gelu
// 256 threads = 8 warps (4 M x 2 N), warp tile 32x32.
// ---------------------------------------------------------------------------
__global__ __launch_bounds__(256) void gemm_tf32_kernel(
    const float* __restrict__ A, int lda,
    const float* __restrict__ W0, const float* __restrict__ bias0, int op0,
    const float* __restrict__ W1, const float* __restrict__ bias1, int op1,
    int splitJ, int K,
    float* __restrict__ out, int ldo)
{
    // NSTAGE * (BM + BN) * PAD floats = 3 * 192 * 20 = 11520 floats = 45 KB
    __shared__ float smem_all[NSTAGE * (BM + BN) * PAD];

    const int m0 = blockIdx.x * BM;
    const int j0 = blockIdx.y * BN;

    const float* W = W0;
    const float* bias = bias0;
    int op = op0;
    int jw = j0;
    if (j0 >= splitJ) { W = W1; bias = bias1; op = op1; jw = j0 - splitJ; }

    const int tid  = threadIdx.x;
    const int warp = tid >> 5;
    const int lane = tid & 31;
    const int wm = (warp & 3) * 32;   // warp row offset
    const int wn = (warp >> 2) * 32;  // warp col offset

    const int niters = K / BKG;

    // Per-thread load slots: 768 float4 per stage (A: 512, B: 256) / 256 thr = 3
    auto issue_load = [&](int it, int buf) {
        float* sa = smem_all + buf * (BM + BN) * PAD;
        float* sb = sa + BM * PAD;
        int kb = it * BKG;
        #pragma unroll
        for (int i = 0; i < 3; i++) {
            int idx = tid + i * 256;
            if (idx < 512) {
                int r  = idx >> 2;
                int c4 = (idx & 3) << 2;
                cp_async16(&sa[r * PAD + c4], &A[(size_t)(m0 + r) * lda + kb + c4]);
            } else {
                int j  = idx - 512;
                int r  = j >> 2;
                int c4 = (j & 3) << 2;
                cp_async16(&sb[r * PAD + c4], &W[(size_t)(jw + r) * K + kb + c4]);
            }
        }
    };

    wmma::fragment<wmma::accumulator, 16, 16, 8, float> c[2][2];
    #pragma unroll
    for (int i = 0; i < 2; i++)
        #pragma unroll
        for (int j = 0; j < 2; j++)
            wmma::fill_fragment(c[i][j], 0.0f);

    // Prologue: prefetch 2 stages
    issue_load(0, 0); cp_commit();
    if (niters > 1) issue_load(1, 1);
    cp_commit();

    for (int it = 0; it < niters; it++) {
        if (it + 2 < niters) issue_load(it + 2, (it + 2) % NSTAGE);
        cp_commit();
        cp_wait<2>();          // stage `it` complete; 2 newer groups may remain
        __syncthreads();

        float* sa = smem_all + (it % NSTAGE) * (BM + BN) * PAD;
        float* sb = sa + BM * PAD;

        #pragma unroll
        for (int kk = 0; kk < BKG; kk += 8) {
            wmma::fragment<wmma::matrix_a, 16, 16, 8, wmma::precision::tf32, wmma::row_major> af[2];
            wmma::fragment<wmma::matrix_b, 16, 16, 8, wmma::precision::tf32, wmma::col_major> bf[2];
            #pragma unroll
            for (int mf = 0; mf < 2; mf++) {
                wmma::load_matrix_sync(af[mf], &sa[(wm + mf * 16) * PAD + kk], PAD);
                #pragma unroll
                for (int t = 0; t < af[mf].num_elements; t++)
                    af[mf].x[t] = wmma::__float_to_tf32(af[mf].x[t]);
            }
            #pragma unroll
            for (int nf = 0; nf < 2; nf++) {
                wmma::load_matrix_sync(bf[nf], &sb[(wn + nf * 16) * PAD + kk], PAD);
                #pragma unroll
                for (int t = 0; t < bf[nf].num_elements; t++)
                    bf[nf].x[t] = wmma::__float_to_tf32(bf[nf].x[t]);
            }
            #pragma unroll
            for (int mf = 0; mf < 2; mf++)
                #pragma unroll
                for (int nf = 0; nf < 2; nf++)
                    wmma::mma_sync(c[mf][nf], af[mf], bf[nf], c[mf][nf]);
        }
        __syncthreads();   // all warps done reading this buffer before refill
    }

    // Epilogue: per-warp smem staging (32x32 at pitch 36), bias + op, store.
    float* stage = smem_all + warp * (32 * 36);   // 8 * 1152 = 9216 floats <= 11520
    #pragma unroll
    for (int mf = 0; mf < 2; mf++) {
        wmma::store_matrix_sync(stage + mf * 16 * 36,      c[mf][0], 36, wmma::mem_row_major);
        wmma::store_matrix_sync(stage + mf * 16 * 36 + 16, c[mf][1], 36, wmma::mem_row_major);
    }
    __syncwarp();
    #pragma unroll
    for (int i = 0; i < 8; i++) {
        int idx = lane + i * 32;        // 0..255
        int r   = idx >> 3;             // 0..31
        int c4  = (idx & 7) << 2;       // 0..28
        float4 v = *reinterpret_cast<float4*>(&stage[r * 36 + c4]);
        float vv[4] = {v.x, v.y, v.z, v.w};
        #pragma unroll
        for (int t = 0; t < 4; t++) {
            float b = bias[jw + wn + c4 + t];
            float x = vv[t] + b;
            if (op == 1)      x = sigmoid_f(x);
            else if (op == 2) x = gelu_exact(x);
            vv[t] = x;
        }
        *reinterpret_cast<float4*>(
            &out[(size_t)(m0 + wm + r) * ldo + j0 + wn + c4]) =
            make_float4(vv[0], vv[1], vv[2], vv[3]);
    }
}

// ---------------------------------------------------------------------------
// Pass A: per-chunk sums of the combined-gelu h (gelu already applied).
// ---------------------------------------------------------------------------
__global__ __launch_bounds__(256) void chunk_sum_kernel() {
    const int b  = blockIdx.x / NCHUNK;
    const int ch = blockIdx.x % NCHUNK;
    const int d  = threadIdx.x;  // 0..255

    float s_lo = 0.0f, s_hi = 0.0f;
    size_t base = ((size_t)(b * NN + ch * CHUNK)) * 1024 + 512;
    #pragma unroll 4
    for (int r = 0; r < CHUNK; r++) {
        float g1 = g_sh[base + (size_t)r * 1024 + d];
        float g2 = g_sh[base + (size_t)r * 1024 + 256 + d];
        s_lo += g1;
        s_hi += g1 * g2;
    }
    int pb = (b * NCHUNK + ch) * DE;
    g_part[pb + d]       = s_lo;
    g_part[pb + 256 + d] = s_hi;
}

// ---------------------------------------------------------------------------
// Block-parallel exclusive scan of chunk partials along the chunk axis.
// ---------------------------------------------------------------------------
__global__ __launch_bounds__(256) void scan_part_kernel() {
    const int b = blockIdx.x / DE;
    const int d = blockIdx.x % DE;
    const int c = threadIdx.x;          // 0..255 == NCHUNK
    const int lane = c & 31;
    const int wid  = c >> 5;

    int idx = (b * NCHUNK + c) * DE + d;
    float v = g_part[idx];

    float x = v;
    #pragma unroll
    for (int off = 1; off < 32; off <<= 1) {
        float y = __shfl_up_sync(0xFFFFFFFFu, x, off);
        if (lane >= off) x += y;
    }

    __shared__ float wsum[8];
    if (lane == 31) wsum[wid] = x;
    __syncthreads();

    __shared__ float woff[8];
    if (wid == 0 && lane < 8) {
        float t = wsum[lane];
        #pragma unroll
        for (int off = 1; off < 8; off <<= 1) {
            float y = __shfl_up_sync(0xFFu, t, off);
            if (lane >= off) t += y;
        }
        woff[lane] = t;
    }
    __syncthreads();

    float base = (wid == 0) ? 0.0f : woff[wid - 1];
    g_part[idx] = base + x - v;   // exclusive prefix
}

// ---------------------------------------------------------------------------
// Pass B: within-chunk inclusive scan with exclusive offset, then
//   o = gate * agg / (m+1 + 1e-7)
// ---------------------------------------------------------------------------
__global__ __launch_bounds__(256) void scan_apply_kernel() {
    const int b  = blockIdx.x / NCHUNK;
    const int ch = blockIdx.x % NCHUNK;
    const int d  = threadIdx.x;  // 0..255

    int pb = (b * NCHUNK + ch) * DE;
    float run_lo = g_part[pb + d];
    float run_hi = g_part[pb + 256 + d];

    #pragma unroll 4
    for (int r = 0; r < CHUNK; r++) {
        int n = ch * CHUNK + r;
        size_t row = (size_t)(b * NN + n);
        float g1 = g_sh[row * 1024 + 512 + d];
        float g2 = g_sh[row * 1024 + 768 + d];
        run_lo += g1;
        run_hi += g1 * g2;

        float rec = 1.0f / ((float)(n + 1) + 1e-7f);
        float gate1 = g_sh[row * 1024 + d];
        float gate2 = g_sh[row * 1024 + 256 + d];
        g_o[row * DE + d]       = gate1 * run_lo * rec;
        g_o[row * DE + 256 + d] = gate2 * run_hi * rec;
    }
}

// ---------------------------------------------------------------------------
// Launcher
// ---------------------------------------------------------------------------
extern "C" void kernel_launch(void* const* d_in, const int* in_sizes, int n_in,
                              void* d_out, int out_size) {
    const float* xq   = (const float*)d_in[0];
    const float* W_se = (const float*)d_in[2];
    const float* b_se = (const float*)d_in[3];
    const float* W_po = (const float*)d_in[4];
    const float* b_po = (const float*)d_in[5];
    const float* W_ag = (const float*)d_in[6];
    const float* b_ag = (const float*)d_in[7];
    float* out = (float*)d_out;

    float* sh_ptr = nullptr;
    float* o_ptr  = nullptr;
    cudaGetSymbolAddress((void**)&sh_ptr, g_sh);
    cudaGetSymbolAddress((void**)&o_ptr, g_o);

    // GEMM1+2 fused: [16384,128] x [1024,128]^T -> gate | gelu(h)
    {
        dim3 grid(TOT / BM, 1024 / BN);   // (128, 16)
        gemm_tf32_kernel<<<grid, 256>>>(
            xq, DIMV,
            W_se, b_se, /*op=*/1,
            W_po, b_po, /*op=*/2,
            /*splitJ=*/DE, /*K=*/DIMV,
            sh_ptr, /*ldo=*/1024);
    }

    chunk_sum_kernel<<<BB * NCHUNK, 256>>>();
    scan_part_kernel<<<BB * DE, 256>>>();
    scan_apply_kernel<<<BB * NCHUNK, 256>>>();

    // GEMM3: [16384,512] x [128,512]^T -> out
    {
        dim3 grid(TOT / BM, DIMV / BN);   // (128, 2)
        gemm_tf32_kernel<<<grid, 256>>>(
            o_ptr, DE,
            W_ag, b_ag, /*op=*/0,
            W_ag, b_ag, /*op=*/0,
            /*splitJ=*/1 << 30, /*K=*/DE,
            out, /*ldo=*/DIMV);
    }
}